// round 14
// baseline (speedup 1.0000x reference)
#include <cuda_runtime.h>
#include <math.h>
#include <stdint.h>

#define SEQ    2048
#define DM     1024
#define NH     16
#define DEP    64
#define BATCHN 4
#define MROWS  (BATCHN*SEQ)   /* 8192 */
#define BHN    (BATCHN*NH)    /* 64   */

// Scratch (allocation-free rule: __device__ globals). q/k/v/multi hold tf32
// bit-patterns (valid fp32 values with low mantissa bits zero).
__device__ uint32_t g_q[(size_t)BHN*SEQ*DEP];
__device__ uint32_t g_k[(size_t)BHN*SEQ*DEP];
__device__ uint32_t g_v[(size_t)BHN*SEQ*DEP];
__device__ uint32_t g_multi[(size_t)MROWS*DM];
// Pre-converted tf32 operands
__device__ uint32_t g_xt [(size_t)MROWS*DM];
__device__ uint32_t g_wqt[(size_t)DM*DM];
__device__ uint32_t g_wkt[(size_t)DM*DM];
__device__ uint32_t g_wvt[(size_t)DM*DM];
__device__ uint32_t g_wot[(size_t)DM*DM];

// ---------------------------------------------------------------------------
// helpers
// ---------------------------------------------------------------------------
__device__ __forceinline__ uint32_t f2tf(float x) {
    uint32_t u;
    asm("cvt.rna.tf32.f32 %0, %1;" : "=r"(u) : "f"(x));
    return u;
}
__device__ __forceinline__ uint32_t smem_u32(const void* p) {
    return (uint32_t)__cvta_generic_to_shared(p);
}
#define CP16(dst_u32, src_ptr) \
    asm volatile("cp.async.cg.shared.global [%0], [%1], 16;" :: "r"(dst_u32), "l"(src_ptr))
#define CP_COMMIT() asm volatile("cp.async.commit_group;")
#define CP_WAIT0()  asm volatile("cp.async.wait_group 0;")
#define CP_WAIT1()  asm volatile("cp.async.wait_group 1;")

// ldmatrix x4: four 8x8 b16 tiles == one 16x8 tf32 A-fragment (or two 8x8
// K-fragments). All 32 lanes supply row addresses.
__device__ __forceinline__ void ldsm4(uint32_t& r0, uint32_t& r1,
                                      uint32_t& r2, uint32_t& r3, uint32_t addr)
{
    asm volatile("ldmatrix.sync.aligned.m8n8.x4.shared.b16 {%0,%1,%2,%3}, [%4];"
        : "=r"(r0), "=r"(r1), "=r"(r2), "=r"(r3) : "r"(addr));
}

// D += A(16x8, row) * B(8x8, col)  tf32 -> f32
__device__ __forceinline__ void mma8(float* c,
    uint32_t a0, uint32_t a1, uint32_t a2, uint32_t a3,
    uint32_t b0, uint32_t b1)
{
    asm volatile(
        "mma.sync.aligned.m16n8k8.row.col.f32.tf32.tf32.f32 "
        "{%0,%1,%2,%3}, {%4,%5,%6,%7}, {%8,%9}, {%0,%1,%2,%3};"
        : "+f"(c[0]), "+f"(c[1]), "+f"(c[2]), "+f"(c[3])
        : "r"(a0), "r"(a1), "r"(a2), "r"(a3), "r"(b0), "r"(b1));
}

// ---------------------------------------------------------------------------
// Fused elementwise fp32 -> tf32-bits conversion for x + 4 weight matrices
// ---------------------------------------------------------------------------
#define XW4 ((MROWS * DM) / 4)   /* 2,097,152 */
#define WW4 ((DM * DM) / 4)      /*   262,144 */

__global__ __launch_bounds__(256) void conv_all(
    const float4* __restrict__ x,
    const float4* __restrict__ wq, const float4* __restrict__ wk,
    const float4* __restrict__ wv, const float4* __restrict__ wo,
    uint4* __restrict__ xt,
    uint4* __restrict__ wqt, uint4* __restrict__ wkt,
    uint4* __restrict__ wvt, uint4* __restrict__ wot)
{
    int i = blockIdx.x * blockDim.x + threadIdx.x;
    const float4* src; uint4* dst; int j;
    if (i < XW4)                 { src = x;  dst = xt;  j = i; }
    else if (i < XW4 + WW4)      { src = wq; dst = wqt; j = i - XW4; }
    else if (i < XW4 + 2 * WW4)  { src = wk; dst = wkt; j = i - XW4 - WW4; }
    else if (i < XW4 + 3 * WW4)  { src = wv; dst = wvt; j = i - XW4 - 2 * WW4; }
    else if (i < XW4 + 4 * WW4)  { src = wo; dst = wot; j = i - XW4 - 3 * WW4; }
    else return;
    float4 v = src[j];
    dst[j] = make_uint4(f2tf(v.x), f2tf(v.y), f2tf(v.z), f2tf(v.w));
}

// ---------------------------------------------------------------------------
// tf32 GEMM: 3-stage cp.async pipeline, ldmatrix A-fragments.
// C[8192,1024] = A[8192,1024] * W + bias.  A/W already tf32 bits.
// MODE 0: W row-major [K,N], C = final fp32 output
// MODE 1: W = [H][K][64] stacked, C = tf32 bits stored as [BH][S][64]
// 128x128 block, BK=32, 256 threads (8 warps of 64x32), m16n8k8.
// ---------------------------------------------------------------------------
#define AS_ST 36
#define BS_ST 136
#define ABUF  (128 * AS_ST)
#define BBUF  (32  * BS_ST)
#define NSTAGE 3
#define GEMM_SMEM_BYTES (NSTAGE * (ABUF + BBUF) * 4)   /* 107520 */
#define NCHUNK (DM / 32)

template<int MODE>
__device__ __forceinline__ void gemm_body(
    const uint32_t* __restrict__ A, const uint32_t* __restrict__ W,
    const float* __restrict__ bias, void* __restrict__ Cv)
{
    extern __shared__ uint32_t gsm[];
    uint32_t* As = gsm;
    uint32_t* Bs = gsm + NSTAGE * ABUF;

    const int tid  = threadIdx.x;
    const int m0   = blockIdx.y * 128;
    const int n0   = blockIdx.x * 128;
    const int warp = tid >> 5;
    const int lane = tid & 31;
    const int g    = lane >> 2;
    const int t    = lane & 3;
    const int wm   = (warp >> 2) * 64;
    const int wn   = (warp & 3) * 32;
    // ldmatrix lane->address mapping for 16x8 tf32 A-fragment
    const int lrow  = lane & 15;            // row within 16-row tile
    const int lkoff = (lane >> 4) << 2;     // 0 or 4 (k half)

    const int arow = tid >> 3;
    const int ac4  = (tid & 7) << 2;
    const int brow = tid >> 5;
    const int bc4  = (tid & 31) << 2;

    float acc[4][4][4];
#pragma unroll
    for (int mi = 0; mi < 4; mi++)
#pragma unroll
        for (int ni = 0; ni < 4; ni++)
#pragma unroll
            for (int r = 0; r < 4; r++) acc[mi][ni][r] = 0.f;

    auto issue = [&](int kt, int buf) {
        uint32_t* Ab = As + buf * ABUF;
        uint32_t* Bb = Bs + buf * BBUF;
#pragma unroll
        for (int p = 0; p < 4; p++) {
            int row = p * 32 + arow;
            CP16(smem_u32(&Ab[row * AS_ST + ac4]),
                 A + (size_t)(m0 + row) * DM + kt + ac4);
        }
#pragma unroll
        for (int p = 0; p < 4; p++) {
            int row = p * 8 + brow;
            const uint32_t* src;
            if (MODE == 0) {
                src = W + (size_t)(kt + row) * DM + n0 + bc4;
            } else {
                int n = n0 + bc4;
                src = W + (size_t)(n >> 6) * (DM * DEP) + (size_t)(kt + row) * DEP + (n & 63);
            }
            CP16(smem_u32(&Bb[row * BS_ST + bc4]), src);
        }
        CP_COMMIT();
    };

    auto compute = [&](int buf) {
        const uint32_t* Ab = As + buf * ABUF;
        const uint32_t* Bb = Bs + buf * BBUF;
#pragma unroll
        for (int kk = 0; kk < 4; kk++) {
            const int k = kk * 8;
            uint32_t a[4][4];
#pragma unroll
            for (int mi = 0; mi < 4; mi++)
                ldsm4(a[mi][0], a[mi][1], a[mi][2], a[mi][3],
                      smem_u32(&Ab[(wm + mi * 16 + lrow) * AS_ST + k + lkoff]));
#pragma unroll
            for (int ni = 0; ni < 4; ni++) {
                uint32_t b0 = Bb[(k + t)     * BS_ST + wn + ni * 8 + g];
                uint32_t b1 = Bb[(k + t + 4) * BS_ST + wn + ni * 8 + g];
#pragma unroll
                for (int mi = 0; mi < 4; mi++)
                    mma8(acc[mi][ni], a[mi][0], a[mi][1], a[mi][2], a[mi][3], b0, b1);
            }
        }
    };

    issue(0, 0);
    issue(32, 1);
#pragma unroll 1
    for (int c = 0; c < NCHUNK; c++) {
        if (c < NCHUNK - 1) CP_WAIT1(); else CP_WAIT0();
        __syncthreads();
        if (c + 2 < NCHUNK)
            issue((c + 2) * 32, (c + 2) % NSTAGE);
        compute(c % NSTAGE);
    }

#pragma unroll
    for (int mi = 0; mi < 4; mi++) {
        int row0 = m0 + wm + mi * 16 + g;
#pragma unroll
        for (int ni = 0; ni < 4; ni++) {
            int col = n0 + wn + ni * 8 + 2 * t;
            float bx = bias[col], by = bias[col + 1];
#pragma unroll
            for (int h = 0; h < 2; h++) {
                int row = row0 + h * 8;
                float vx = acc[mi][ni][h * 2 + 0] + bx;
                float vy = acc[mi][ni][h * 2 + 1] + by;
                if (MODE == 0) {
                    *(float2*)&((float*)Cv)[(size_t)row * DM + col] = make_float2(vx, vy);
                } else {
                    int b = row >> 11, s = row & 2047;
                    int hh = col >> 6, e = col & 63;
                    *(uint2*)&((uint32_t*)Cv)[(((size_t)(b * NH + hh)) * SEQ + s) * DEP + e]
                        = make_uint2(f2tf(vx), f2tf(vy));
                }
            }
        }
    }
}

__global__ __launch_bounds__(256, 2) void gemm_qkv(
    const uint32_t* __restrict__ x,
    const uint32_t* __restrict__ Wq, const uint32_t* __restrict__ Wk, const uint32_t* __restrict__ Wv,
    const float* __restrict__ bq, const float* __restrict__ bk, const float* __restrict__ bv,
    uint32_t* __restrict__ qo, uint32_t* __restrict__ ko, uint32_t* __restrict__ vo)
{
    int z = blockIdx.z;
    const uint32_t* W = (z == 0) ? Wq : (z == 1) ? Wk : Wv;
    const float*    b = (z == 0) ? bq : (z == 1) ? bk : bv;
    uint32_t*       C = (z == 0) ? qo : (z == 1) ? ko : vo;
    gemm_body<1>(x, W, b, C);
}

__global__ __launch_bounds__(256, 2) void gemm_out(
    const uint32_t* __restrict__ A, const uint32_t* __restrict__ W,
    const float* __restrict__ bias, float* __restrict__ C)
{
    gemm_body<0>(A, W, bias, C);
}

// ---------------------------------------------------------------------------
// Tensor-core flash attention: ldmatrix fragments + double-buffered 32-row
// K/V tiles (cp.async overlap). Block = 128 threads (4 warps), warp owns
// 32 q-rows (2 m-tiles), QROWS=128. Smem 105472 B -> 2 CTAs/SM.
// ---------------------------------------------------------------------------
#define Q_ST 68
#define V_ST 72
#define QROWS 128
#define KT   32                                /* key-tile rows */
#define NIT  (SEQ / KT)                        /* 64 */
#define OFF_Q  0
#define OFF_P  (QROWS * Q_ST)                  /* 8704  */
#define OFF_K0 (OFF_P + QROWS * Q_ST)          /* 17408 */
#define OFF_K1 (OFF_K0 + KT * Q_ST)            /* 19584 */
#define OFF_V0 (OFF_K1 + KT * Q_ST)            /* 21760 */
#define OFF_V1 (OFF_V0 + KT * V_ST)            /* 24064 */
#define ATT_SMEM_WORDS (OFF_V1 + KT * V_ST)    /* 26368 -> 105472 B */

__global__ __launch_bounds__(128) void attn_tc(
    const uint32_t* __restrict__ q, const uint32_t* __restrict__ k,
    const uint32_t* __restrict__ v, uint32_t* __restrict__ multi)
{
    extern __shared__ uint32_t sm[];
    uint32_t* Qs = sm + OFF_Q;
    uint32_t* Ps = sm + OFF_P;
    uint32_t* Kb[2] = { sm + OFF_K0, sm + OFF_K1 };
    uint32_t* Vb[2] = { sm + OFF_V0, sm + OFF_V1 };

    const int tid  = threadIdx.x;
    const int warp = tid >> 5;
    const int lane = tid & 31;
    const int g    = lane >> 2;
    const int t    = lane & 3;
    const int bh   = blockIdx.y;
    const int qt   = blockIdx.x;
    const int mb[2] = { warp * 32, warp * 32 + 16 };
    // ldmatrix lane mappings
    const int lrow  = lane & 15;                 // A-fragment: row in 16-row tile
    const int lkoff = (lane >> 4) << 2;          // A-fragment: k half (0/4)
    const int knsel = lane >> 4;                 // K-fragment: nt pair member
    const int kcsel = ((lane >> 3) & 1) << 2;    // K-fragment: k half (0/4)
    const int krow  = lane & 7;                  // K-fragment: row in 8-row tile

    // ---- load Q 128x64: already tf32-rounded; scale by 1/8 (exact pow2) ----
    {
        const float* qp = (const float*)(q + ((size_t)bh * SEQ + qt * QROWS) * DEP);
#pragma unroll
        for (int p = 0; p < 16; p++) {
            int f4  = p * 128 + tid;
            int row = f4 >> 4;
            int c4  = (f4 & 15) << 2;
            float4 vv = *(const float4*)(qp + (size_t)row * DEP + c4);
            uint32_t* dst = &Qs[row * Q_ST + c4];
            dst[0] = __float_as_uint(vv.x * 0.125f);
            dst[1] = __float_as_uint(vv.y * 0.125f);
            dst[2] = __float_as_uint(vv.z * 0.125f);
            dst[3] = __float_as_uint(vv.w * 0.125f);
        }
    }

    float mr[2][2], l[2][2];
    float O[2][8][4];
#pragma unroll
    for (int mi = 0; mi < 2; mi++) {
        mr[mi][0] = mr[mi][1] = -1e30f;
        l[mi][0] = l[mi][1] = 0.f;
#pragma unroll
        for (int dt = 0; dt < 8; dt++)
#pragma unroll
            for (int r = 0; r < 4; r++) O[mi][dt][r] = 0.f;
    }

    const uint32_t* kbase = k + (size_t)bh * SEQ * DEP;
    const uint32_t* vbase = v + (size_t)bh * SEQ * DEP;

    auto issue_tile = [&](int t0, int bi) {
#pragma unroll
        for (int p = 0; p < 4; p++) {
            int f4  = p * 128 + tid;
            int row = f4 >> 4;
            int c4  = (f4 & 15) << 2;
            CP16(smem_u32(&Kb[bi][row * Q_ST + c4]), kbase + (size_t)(t0 + row) * DEP + c4);
            CP16(smem_u32(&Vb[bi][row * V_ST + c4]), vbase + (size_t)(t0 + row) * DEP + c4);
        }
        CP_COMMIT();
    };

    issue_tile(0, 0);

#pragma unroll 1
    for (int c = 0; c < NIT; c++) {
        const int bi = c & 1;
        CP_WAIT0();          // tile c landed (only group pending)
        __syncthreads();     // visible to all; all warps done reading buf bi
        if (c + 1 < NIT)
            issue_tile((c + 1) * KT, bi ^ 1);   // in flight during compute
        const uint32_t* Ks = Kb[bi];
        const uint32_t* Vs = Vb[bi];

        // ---- S = Q K^T : ldmatrix A (Q) and B (K) fragments ----
        float s[2][4][4];
#pragma unroll
        for (int mi = 0; mi < 2; mi++)
#pragma unroll
            for (int nt = 0; nt < 4; nt++)
#pragma unroll
                for (int r = 0; r < 4; r++) s[mi][nt][r] = 0.f;

#pragma unroll
        for (int kk = 0; kk < 8; kk++) {
            const int kb = kk * 8;
            uint32_t a[2][4];
#pragma unroll
            for (int mi = 0; mi < 2; mi++)
                ldsm4(a[mi][0], a[mi][1], a[mi][2], a[mi][3],
                      smem_u32(&Qs[(mb[mi] + lrow) * Q_ST + kb + lkoff]));
            uint32_t bf[4][2];
#pragma unroll
            for (int ntp = 0; ntp < 2; ntp++) {
                uint32_t d0, d1, d2, d3;
                ldsm4(d0, d1, d2, d3,
                      smem_u32(&Ks[((ntp * 2 + knsel) * 8 + krow) * Q_ST + kb + kcsel]));
                bf[2 * ntp][0] = d0; bf[2 * ntp][1] = d1;
                bf[2 * ntp + 1][0] = d2; bf[2 * ntp + 1][1] = d3;
            }
#pragma unroll
            for (int nt = 0; nt < 4; nt++) {
                mma8(s[0][nt], a[0][0], a[0][1], a[0][2], a[0][3], bf[nt][0], bf[nt][1]);
                mma8(s[1][nt], a[1][0], a[1][1], a[1][2], a[1][3], bf[nt][0], bf[nt][1]);
            }
        }

        // ---- online softmax + P write, per m-tile ----
#pragma unroll
        for (int mi = 0; mi < 2; mi++) {
            float mx0 = -1e30f, mx1 = -1e30f;
#pragma unroll
            for (int nt = 0; nt < 4; nt++) {
                mx0 = fmaxf(mx0, fmaxf(s[mi][nt][0], s[mi][nt][1]));
                mx1 = fmaxf(mx1, fmaxf(s[mi][nt][2], s[mi][nt][3]));
            }
            mx0 = fmaxf(mx0, __shfl_xor_sync(0xffffffffu, mx0, 1));
            mx0 = fmaxf(mx0, __shfl_xor_sync(0xffffffffu, mx0, 2));
            mx1 = fmaxf(mx1, __shfl_xor_sync(0xffffffffu, mx1, 1));
            mx1 = fmaxf(mx1, __shfl_xor_sync(0xffffffffu, mx1, 2));

            float mn0 = fmaxf(mr[mi][0], mx0);
            float mn1 = fmaxf(mr[mi][1], mx1);
            float corr0 = __expf(mr[mi][0] - mn0);
            float corr1 = __expf(mr[mi][1] - mn1);

            float sum0 = 0.f, sum1 = 0.f;
#pragma unroll
            for (int nt = 0; nt < 4; nt++) {
                s[mi][nt][0] = __expf(s[mi][nt][0] - mn0);
                s[mi][nt][1] = __expf(s[mi][nt][1] - mn0);
                s[mi][nt][2] = __expf(s[mi][nt][2] - mn1);
                s[mi][nt][3] = __expf(s[mi][nt][3] - mn1);
                sum0 += s[mi][nt][0] + s[mi][nt][1];
                sum1 += s[mi][nt][2] + s[mi][nt][3];
            }
            sum0 += __shfl_xor_sync(0xffffffffu, sum0, 1);
            sum0 += __shfl_xor_sync(0xffffffffu, sum0, 2);
            sum1 += __shfl_xor_sync(0xffffffffu, sum1, 1);
            sum1 += __shfl_xor_sync(0xffffffffu, sum1, 2);
            l[mi][0] = l[mi][0] * corr0 + sum0;
            l[mi][1] = l[mi][1] * corr1 + sum1;

#pragma unroll
            for (int dt = 0; dt < 8; dt++) {
                O[mi][dt][0] *= corr0; O[mi][dt][1] *= corr0;
                O[mi][dt][2] *= corr1; O[mi][dt][3] *= corr1;
            }

#pragma unroll
            for (int nt = 0; nt < 4; nt++) {
                uint2 p01 = make_uint2(f2tf(s[mi][nt][0]), f2tf(s[mi][nt][1]));
                uint2 p23 = make_uint2(f2tf(s[mi][nt][2]), f2tf(s[mi][nt][3]));
                *(uint2*)&Ps[(mb[mi] + g)     * Q_ST + nt * 8 + 2 * t] = p01;
                *(uint2*)&Ps[(mb[mi] + g + 8) * Q_ST + nt * 8 + 2 * t] = p23;
            }
            mr[mi][0] = mn0;
            mr[mi][1] = mn1;
        }
        __syncwarp();   // Ps rows are warp-private

        // ---- O += P V : ldmatrix P fragments, scalar V ----
#pragma unroll
        for (int kk = 0; kk < 4; kk++) {
            const int kb = kk * 8;
            uint32_t a[2][4];
#pragma unroll
            for (int mi = 0; mi < 2; mi++)
                ldsm4(a[mi][0], a[mi][1], a[mi][2], a[mi][3],
                      smem_u32(&Ps[(mb[mi] + lrow) * Q_ST + kb + lkoff]));
#pragma unroll
            for (int dt = 0; dt < 8; dt++) {
                uint32_t b0 = Vs[(kb + t)     * V_ST + dt * 8 + g];
                uint32_t b1 = Vs[(kb + t + 4) * V_ST + dt * 8 + g];
                mma8(O[0][dt], a[0][0], a[0][1], a[0][2], a[0][3], b0, b1);
                mma8(O[1][dt], a[1][0], a[1][1], a[1][2], a[1][3], b0, b1);
            }
        }
    }

    // ---- normalize + store to multi [B][S][H*64] as tf32 bits ----
    int b = bh >> 4, h = bh & 15;
#pragma unroll
    for (int mi = 0; mi < 2; mi++) {
        float inv0 = 1.f / l[mi][0], inv1 = 1.f / l[mi][1];
        int srow = qt * QROWS + mb[mi] + g;
        uint32_t* op = multi + ((size_t)(b * SEQ) + srow) * DM + h * DEP;
#pragma unroll
        for (int dt = 0; dt < 8; dt++) {
            int col = dt * 8 + 2 * t;
            *(uint2*)(op + col) =
                make_uint2(f2tf(O[mi][dt][0] * inv0), f2tf(O[mi][dt][1] * inv0));
            *(uint2*)(op + 8 * (size_t)DM + col) =
                make_uint2(f2tf(O[mi][dt][2] * inv1), f2tf(O[mi][dt][3] * inv1));
        }
    }
}

// ---------------------------------------------------------------------------
// Launch: fused convert -> fused QKV GEMM -> attention -> output GEMM.
// ---------------------------------------------------------------------------
extern "C" void kernel_launch(void* const* d_in, const int* in_sizes, int n_in,
                              void* d_out, int out_size)
{
    const float* x  = (const float*)d_in[0];
    const float* Wq = (const float*)d_in[1];
    const float* bq = (const float*)d_in[2];
    const float* Wk = (const float*)d_in[3];
    const float* bk = (const float*)d_in[4];
    const float* Wv = (const float*)d_in[5];
    const float* bv = (const float*)d_in[6];
    const float* Wo = (const float*)d_in[7];
    const float* bo = (const float*)d_in[8];
    float* out = (float*)d_out;

    uint32_t *qb, *kb, *vb, *mb, *xt, *wqt, *wkt, *wvt, *wot;
    cudaGetSymbolAddress((void**)&qb,  g_q);
    cudaGetSymbolAddress((void**)&kb,  g_k);
    cudaGetSymbolAddress((void**)&vb,  g_v);
    cudaGetSymbolAddress((void**)&mb,  g_multi);
    cudaGetSymbolAddress((void**)&xt,  g_xt);
    cudaGetSymbolAddress((void**)&wqt, g_wqt);
    cudaGetSymbolAddress((void**)&wkt, g_wkt);
    cudaGetSymbolAddress((void**)&wvt, g_wvt);
    cudaGetSymbolAddress((void**)&wot, g_wot);

    const int att_smem = ATT_SMEM_WORDS * 4;   // 105472 bytes
    cudaFuncSetAttribute(attn_tc,  cudaFuncAttributeMaxDynamicSharedMemorySize, att_smem);
    cudaFuncSetAttribute(gemm_qkv, cudaFuncAttributeMaxDynamicSharedMemorySize, GEMM_SMEM_BYTES);
    cudaFuncSetAttribute(gemm_out, cudaFuncAttributeMaxDynamicSharedMemorySize, GEMM_SMEM_BYTES);

    const int TOT4 = XW4 + 4 * WW4;      // 3,145,728
    conv_all<<<(TOT4 + 255) / 256, 256>>>(
        (const float4*)x, (const float4*)Wq, (const float4*)Wk,
        (const float4*)Wv, (const float4*)Wo,
        (uint4*)xt, (uint4*)wqt, (uint4*)wkt, (uint4*)wvt, (uint4*)wot);

    dim3 gq(DM / 128, MROWS / 128, 3);
    gemm_qkv<<<gq, 256, GEMM_SMEM_BYTES>>>(xt, wqt, wkt, wvt, bq, bk, bv, qb, kb, vb);

    dim3 ga(SEQ / QROWS, BHN);           // (16, 64)
    attn_tc<<<ga, 128, att_smem>>>(qb, kb, vb, mb);

    dim3 gg(DM / 128, MROWS / 128);
    gemm_out<<<gg, 256, GEMM_SMEM_BYTES>>>(mb, wot, bo, out);
}

// round 16
// speedup vs baseline: 1.7373x; 1.7373x over previous
#include <cuda_runtime.h>
#include <cuda_fp16.h>
#include <math.h>
#include <stdint.h>

#define SEQ    2048
#define DM     1024
#define NH     16
#define DEP    64
#define BATCHN 4
#define MROWS  8192
#define BHN    64

// Scratch (allocation-free rule). All buffers hold fp16 (half2 packed in u32).
__device__ uint32_t g_q    [(size_t)BHN*SEQ*DEP/2];
__device__ uint32_t g_k    [(size_t)BHN*SEQ*DEP/2];
__device__ uint32_t g_v    [(size_t)BHN*SEQ*DEP/2];   // [BH][DEP][SEQ] (transposed)
__device__ uint32_t g_multi[(size_t)MROWS*DM/2];
__device__ uint32_t g_xt   [(size_t)MROWS*DM/2];
__device__ uint32_t g_wqt  [(size_t)DM*DM/2];          // [N][K] transposed
__device__ uint32_t g_wkt  [(size_t)DM*DM/2];
__device__ uint32_t g_wvt  [(size_t)DM*DM/2];
__device__ uint32_t g_wot  [(size_t)DM*DM/2];

// ---------------------------------------------------------------------------
// helpers
// ---------------------------------------------------------------------------
__device__ __forceinline__ uint32_t smem_u32(const void* p) {
    return (uint32_t)__cvta_generic_to_shared(p);
}
__device__ __forceinline__ uint32_t fpack(float a, float b) {
    __half2 h = __floats2half2_rn(a, b);
    return *(uint32_t*)&h;
}
#define CP16(dst_u32, src_ptr) \
    asm volatile("cp.async.cg.shared.global [%0], [%1], 16;" :: "r"(dst_u32), "l"(src_ptr))
#define CP_COMMIT() asm volatile("cp.async.commit_group;")
#define CP_WAIT0()  asm volatile("cp.async.wait_group 0;")
#define CP_WAIT1()  asm volatile("cp.async.wait_group 1;")

// D += A(16x16, row) * B(16x8, col)  fp16 -> fp32
__device__ __forceinline__ void mma16(float* c,
    uint32_t a0, uint32_t a1, uint32_t a2, uint32_t a3,
    uint32_t b0, uint32_t b1)
{
    asm volatile(
        "mma.sync.aligned.m16n8k16.row.col.f32.f16.f16.f32 "
        "{%0,%1,%2,%3}, {%4,%5,%6,%7}, {%8,%9}, {%0,%1,%2,%3};"
        : "+f"(c[0]), "+f"(c[1]), "+f"(c[2]), "+f"(c[3])
        : "r"(a0), "r"(a1), "r"(a2), "r"(a3), "r"(b0), "r"(b1));
}

// ---------------------------------------------------------------------------
// Prepass: x -> fp16; weights -> transposed [N][K] fp16
// ---------------------------------------------------------------------------
#define XW4 ((MROWS * DM) / 4)   /* 2,097,152 float4s */

__global__ __launch_bounds__(256) void conv_x(
    const float4* __restrict__ src, uint2* __restrict__ dst, int n4)
{
    int i = blockIdx.x * blockDim.x + threadIdx.x;
    if (i < n4) {
        float4 v = src[i];
        dst[i] = make_uint2(fpack(v.x, v.y), fpack(v.z, v.w));
    }
}

// z = mat*16 + h.  QKV (mat<3): src[h*65536 + k*64 + e] -> dst[(h*64+e)*1024 + k]
//                  WO  (mat=3): src[k*1024 + h*64 + e]  -> dst[(h*64+e)*1024 + k]
__global__ __launch_bounds__(256) void transw(
    const float* __restrict__ wq, const float* __restrict__ wk,
    const float* __restrict__ wv, const float* __restrict__ wo,
    __half* __restrict__ wqt, __half* __restrict__ wkt,
    __half* __restrict__ wvt, __half* __restrict__ wot)
{
    __shared__ float tile[32][33];
    int z = blockIdx.z, mat = z >> 4, h = z & 15;
    const float* src = (mat == 0) ? wq : (mat == 1) ? wk : (mat == 2) ? wv : wo;
    __half*      dst = (mat == 0) ? wqt : (mat == 1) ? wkt : (mat == 2) ? wvt : wot;
    int e0 = blockIdx.x * 32, k0 = blockIdx.y * 32;
    int tx = threadIdx.x, ty = threadIdx.y;
#pragma unroll
    for (int r = 0; r < 4; r++) {
        int k = k0 + ty + r * 8;
        float v = (mat < 3) ? src[(size_t)h * 65536 + (size_t)k * 64 + e0 + tx]
                            : src[(size_t)k * 1024 + h * 64 + e0 + tx];
        tile[ty + r * 8][tx] = v;
    }
    __syncthreads();
#pragma unroll
    for (int r = 0; r < 4; r++) {
        int e = e0 + ty + r * 8;
        dst[(size_t)(h * 64 + e) * 1024 + k0 + tx] = __float2half_rn(tile[tx][ty + r * 8]);
    }
}

// ---------------------------------------------------------------------------
// fp16 GEMM: C[8192,1024] = A * WT^T + bias. A [M][K] half; WT [N][K] half.
// 128x128 tile, BK=64 elems (32 half2 words), 3-stage cp.async, 256 threads.
// MODE 0: fp32 out row-major. MODE 1: half out [BH][S][64].
// MODE 2: half out [BH][DEP][SEQ]  (V transposed for PV B-operand).
// ---------------------------------------------------------------------------
#define GST   36                       /* word stride, 4 mod 32 -> conflict-free */
#define GABUF (128 * GST)              /* 4608 words */
#define GSTAGE 3
#define GSMEM_BYTES (GSTAGE * 2 * GABUF * 4)   /* 110592 */
#define GNCH  (DM / 64)                /* 16 chunks */

template<int MODE>
__device__ __forceinline__ void tgemm_body(
    const uint32_t* __restrict__ A, const uint32_t* __restrict__ WT,
    const float* __restrict__ bias, void* __restrict__ Cv)
{
    extern __shared__ uint32_t gsm[];

    const int tid  = threadIdx.x;
    const int m0   = blockIdx.y * 128;
    const int n0   = blockIdx.x * 128;
    const int warp = tid >> 5;
    const int lane = tid & 31;
    const int g    = lane >> 2;
    const int t    = lane & 3;
    const int wm   = (warp >> 2) * 64;
    const int wn   = (warp & 3) * 32;

    float acc[4][4][4];
#pragma unroll
    for (int mi = 0; mi < 4; mi++)
#pragma unroll
        for (int ni = 0; ni < 4; ni++)
#pragma unroll
            for (int r = 0; r < 4; r++) acc[mi][ni][r] = 0.f;

    auto issue = [&](int ch, int buf) {
        uint32_t* Ab = gsm + buf * (2 * GABUF);
        uint32_t* Bb = Ab + GABUF;
        const int kw = ch * 32;           // k-word base
#pragma unroll
        for (int p = 0; p < 4; p++) {
            int idx = p * 256 + tid;
            int row = idx >> 3;
            int cc  = (idx & 7) << 2;     // word offset within 32-word row
            CP16(smem_u32(&Ab[row * GST + cc]), A  + (size_t)(m0 + row) * 512 + kw + cc);
            CP16(smem_u32(&Bb[row * GST + cc]), WT + (size_t)(n0 + row) * 512 + kw + cc);
        }
        CP_COMMIT();
    };

    auto compute = [&](int buf) {
        const uint32_t* Ab = gsm + buf * (2 * GABUF);
        const uint32_t* Bb = Ab + GABUF;
#pragma unroll
        for (int kk = 0; kk < 4; kk++) {
            const int kbw = kk * 8;
            uint32_t a[4][4];
#pragma unroll
            for (int mi = 0; mi < 4; mi++) {
                int r0 = wm + mi * 16 + g;
                a[mi][0] = Ab[(r0)     * GST + kbw + t];
                a[mi][1] = Ab[(r0 + 8) * GST + kbw + t];
                a[mi][2] = Ab[(r0)     * GST + kbw + t + 4];
                a[mi][3] = Ab[(r0 + 8) * GST + kbw + t + 4];
            }
#pragma unroll
            for (int ni = 0; ni < 4; ni++) {
                uint32_t b0 = Bb[(wn + ni * 8 + g) * GST + kbw + t];
                uint32_t b1 = Bb[(wn + ni * 8 + g) * GST + kbw + t + 4];
#pragma unroll
                for (int mi = 0; mi < 4; mi++)
                    mma16(acc[mi][ni], a[mi][0], a[mi][1], a[mi][2], a[mi][3], b0, b1);
            }
        }
    };

    issue(0, 0);
    issue(1, 1);
#pragma unroll 1
    for (int c = 0; c < GNCH; c++) {
        if (c < GNCH - 1) CP_WAIT1(); else CP_WAIT0();
        __syncthreads();
        if (c + 2 < GNCH) issue(c + 2, (c + 2) % GSTAGE);
        compute(c % GSTAGE);
    }

    // ---- epilogue ----
#pragma unroll
    for (int mi = 0; mi < 4; mi++) {
        int row0 = m0 + wm + mi * 16 + g;
#pragma unroll
        for (int ni = 0; ni < 4; ni++) {
            int col = n0 + wn + ni * 8 + 2 * t;
            float bx = bias[col], by = bias[col + 1];
#pragma unroll
            for (int hlf = 0; hlf < 2; hlf++) {
                int row = row0 + hlf * 8;
                float vx = acc[mi][ni][hlf * 2 + 0] + bx;
                float vy = acc[mi][ni][hlf * 2 + 1] + by;
                int b = row >> 11, s = row & 2047;
                int hh = col >> 6, e = col & 63;
                if (MODE == 0) {
                    *(float2*)&((float*)Cv)[(size_t)row * DM + col] = make_float2(vx, vy);
                } else if (MODE == 1) {
                    ((uint32_t*)Cv)[(((size_t)(b * NH + hh)) * SEQ + s) * 32 + (e >> 1)]
                        = fpack(vx, vy);
                } else {
                    __half* Vh = (__half*)Cv;
                    size_t base = ((size_t)(b * NH + hh) * DEP + e) * SEQ + s;
                    Vh[base]       = __float2half_rn(vx);
                    Vh[base + SEQ] = __float2half_rn(vy);
                }
            }
        }
    }
}

__global__ __launch_bounds__(256, 2) void gemm_qkv(
    const uint32_t* __restrict__ x,
    const uint32_t* __restrict__ WqT, const uint32_t* __restrict__ WkT,
    const uint32_t* __restrict__ WvT,
    const float* __restrict__ bq, const float* __restrict__ bk, const float* __restrict__ bv,
    uint32_t* __restrict__ qo, uint32_t* __restrict__ ko, uint32_t* __restrict__ vo)
{
    int z = blockIdx.z;
    if (z == 0)      tgemm_body<1>(x, WqT, bq, qo);
    else if (z == 1) tgemm_body<1>(x, WkT, bk, ko);
    else             tgemm_body<2>(x, WvT, bv, vo);
}

__global__ __launch_bounds__(256, 2) void gemm_out(
    const uint32_t* __restrict__ A, const uint32_t* __restrict__ WoT,
    const float* __restrict__ bias, float* __restrict__ C)
{
    tgemm_body<0>(A, WoT, bias, C);
}

// ---------------------------------------------------------------------------
// fp16 flash attention. Q [bh][s][32w], K [bh][s][32w], V [bh][d][1024w].
// 128 threads (4 warps), warp owns 32 q-rows (2 m-tiles), 64-key tiles.
// Smem: Q 128x36 + K 64x36 + P 128x36 + V 64x36 = 13824 w = 55296 B.
// ---------------------------------------------------------------------------
#define AST 36
#define OFF_Q 0
#define OFF_K (128 * AST)              /* 4608 */
#define OFF_P (OFF_K + 64 * AST)       /* 6912 */
#define OFF_V (OFF_P + 128 * AST)      /* 11520 */
#define ATT_SMEM_BYTES ((OFF_V + 64 * AST) * 4)   /* 55296 */

__global__ __launch_bounds__(128) void attn_tc(
    const uint32_t* __restrict__ q, const uint32_t* __restrict__ k,
    const uint32_t* __restrict__ v, uint32_t* __restrict__ multi)
{
    extern __shared__ uint32_t sm[];
    uint32_t* Qs = sm + OFF_Q;
    uint32_t* Ks = sm + OFF_K;
    uint32_t* Ps = sm + OFF_P;
    uint32_t* Vs = sm + OFF_V;

    const int tid  = threadIdx.x;
    const int warp = tid >> 5;
    const int lane = tid & 31;
    const int g    = lane >> 2;
    const int t    = lane & 3;
    const int bh   = blockIdx.y;
    const int qt   = blockIdx.x;
    const int mb[2] = { warp * 32, warp * 32 + 16 };

    // ---- load Q 128x64 (half), scale by 1/8 (exact pow2) ----
    {
        const uint32_t* qp = q + ((size_t)bh * SEQ + qt * 128) * 32;
        const __half2 sc = __float2half2_rn(0.125f);
#pragma unroll
        for (int p = 0; p < 8; p++) {
            int f4  = p * 128 + tid;
            int row = f4 >> 3;
            int c4  = (f4 & 7) << 2;
            uint4 w = *(const uint4*)(qp + row * 32 + c4);
            __half2* hw = (__half2*)&w;
            hw[0] = __hmul2(hw[0], sc); hw[1] = __hmul2(hw[1], sc);
            hw[2] = __hmul2(hw[2], sc); hw[3] = __hmul2(hw[3], sc);
            *(uint4*)&Qs[row * AST + c4] = w;
        }
    }

    float mr[2][2], l[2][2];
    float O[2][8][4];
#pragma unroll
    for (int mi = 0; mi < 2; mi++) {
        mr[mi][0] = mr[mi][1] = -1e30f;
        l[mi][0] = l[mi][1] = 0.f;
#pragma unroll
        for (int dt = 0; dt < 8; dt++)
#pragma unroll
            for (int r = 0; r < 4; r++) O[mi][dt][r] = 0.f;
    }

    const uint32_t* kbase = k + (size_t)bh * SEQ * 32;
    const uint32_t* vbase = v + (size_t)bh * DEP * 1024;

#pragma unroll 1
    for (int t0 = 0; t0 < SEQ; t0 += 64) {
        __syncthreads();
        // K tile: 64 s-rows x 32 words; V tile: 64 d-rows x 32 s-words
#pragma unroll
        for (int p = 0; p < 4; p++) {
            int idx = p * 128 + tid;
            int row = idx >> 3;
            int cc  = (idx & 7) << 2;
            CP16(smem_u32(&Ks[row * AST + cc]), kbase + (size_t)(t0 + row) * 32 + cc);
            CP16(smem_u32(&Vs[row * AST + cc]), vbase + (size_t)row * 1024 + (t0 >> 1) + cc);
        }
        CP_COMMIT();
        CP_WAIT0();
        __syncthreads();

        // ---- S = Q K^T (k = depth, 4 k16 steps) ----
        float s[2][8][4];
#pragma unroll
        for (int mi = 0; mi < 2; mi++)
#pragma unroll
            for (int nt = 0; nt < 8; nt++)
#pragma unroll
                for (int r = 0; r < 4; r++) s[mi][nt][r] = 0.f;

#pragma unroll
        for (int kk = 0; kk < 4; kk++) {
            const int kbw = kk * 8;
            uint32_t a[2][4];
#pragma unroll
            for (int mi = 0; mi < 2; mi++) {
                a[mi][0] = Qs[(mb[mi] + g)     * AST + kbw + t];
                a[mi][1] = Qs[(mb[mi] + g + 8) * AST + kbw + t];
                a[mi][2] = Qs[(mb[mi] + g)     * AST + kbw + t + 4];
                a[mi][3] = Qs[(mb[mi] + g + 8) * AST + kbw + t + 4];
            }
#pragma unroll
            for (int nt = 0; nt < 8; nt++) {
                uint32_t b0 = Ks[(nt * 8 + g) * AST + kbw + t];
                uint32_t b1 = Ks[(nt * 8 + g) * AST + kbw + t + 4];
                mma16(s[0][nt], a[0][0], a[0][1], a[0][2], a[0][3], b0, b1);
                mma16(s[1][nt], a[1][0], a[1][1], a[1][2], a[1][3], b0, b1);
            }
        }

        // ---- online softmax + P write ----
#pragma unroll
        for (int mi = 0; mi < 2; mi++) {
            float mx0 = -1e30f, mx1 = -1e30f;
#pragma unroll
            for (int nt = 0; nt < 8; nt++) {
                mx0 = fmaxf(mx0, fmaxf(s[mi][nt][0], s[mi][nt][1]));
                mx1 = fmaxf(mx1, fmaxf(s[mi][nt][2], s[mi][nt][3]));
            }
            mx0 = fmaxf(mx0, __shfl_xor_sync(0xffffffffu, mx0, 1));
            mx0 = fmaxf(mx0, __shfl_xor_sync(0xffffffffu, mx0, 2));
            mx1 = fmaxf(mx1, __shfl_xor_sync(0xffffffffu, mx1, 1));
            mx1 = fmaxf(mx1, __shfl_xor_sync(0xffffffffu, mx1, 2));

            float mn0 = fmaxf(mr[mi][0], mx0);
            float mn1 = fmaxf(mr[mi][1], mx1);
            float corr0 = __expf(mr[mi][0] - mn0);
            float corr1 = __expf(mr[mi][1] - mn1);

            float sum0 = 0.f, sum1 = 0.f;
#pragma unroll
            for (int nt = 0; nt < 8; nt++) {
                s[mi][nt][0] = __expf(s[mi][nt][0] - mn0);
                s[mi][nt][1] = __expf(s[mi][nt][1] - mn0);
                s[mi][nt][2] = __expf(s[mi][nt][2] - mn1);
                s[mi][nt][3] = __expf(s[mi][nt][3] - mn1);
                sum0 += s[mi][nt][0] + s[mi][nt][1];
                sum1 += s[mi][nt][2] + s[mi][nt][3];
            }
            sum0 += __shfl_xor_sync(0xffffffffu, sum0, 1);
            sum0 += __shfl_xor_sync(0xffffffffu, sum0, 2);
            sum1 += __shfl_xor_sync(0xffffffffu, sum1, 1);
            sum1 += __shfl_xor_sync(0xffffffffu, sum1, 2);
            l[mi][0] = l[mi][0] * corr0 + sum0;
            l[mi][1] = l[mi][1] * corr1 + sum1;

#pragma unroll
            for (int dt = 0; dt < 8; dt++) {
                O[mi][dt][0] *= corr0; O[mi][dt][1] *= corr0;
                O[mi][dt][2] *= corr1; O[mi][dt][3] *= corr1;
            }

#pragma unroll
            for (int nt = 0; nt < 8; nt++) {
                Ps[(mb[mi] + g)     * AST + nt * 4 + t] = fpack(s[mi][nt][0], s[mi][nt][1]);
                Ps[(mb[mi] + g + 8) * AST + nt * 4 + t] = fpack(s[mi][nt][2], s[mi][nt][3]);
            }
            mr[mi][0] = mn0;
            mr[mi][1] = mn1;
        }
        __syncwarp();   // Ps rows are warp-private

        // ---- O += P V (k = keys, 4 k16 steps) ----
#pragma unroll
        for (int kk = 0; kk < 4; kk++) {
            const int kbw = kk * 8;
            uint32_t a[2][4];
#pragma unroll
            for (int mi = 0; mi < 2; mi++) {
                a[mi][0] = Ps[(mb[mi] + g)     * AST + kbw + t];
                a[mi][1] = Ps[(mb[mi] + g + 8) * AST + kbw + t];
                a[mi][2] = Ps[(mb[mi] + g)     * AST + kbw + t + 4];
                a[mi][3] = Ps[(mb[mi] + g + 8) * AST + kbw + t + 4];
            }
#pragma unroll
            for (int dt = 0; dt < 8; dt++) {
                uint32_t b0 = Vs[(dt * 8 + g) * AST + kbw + t];
                uint32_t b1 = Vs[(dt * 8 + g) * AST + kbw + t + 4];
                mma16(O[0][dt], a[0][0], a[0][1], a[0][2], a[0][3], b0, b1);
                mma16(O[1][dt], a[1][0], a[1][1], a[1][2], a[1][3], b0, b1);
            }
        }
    }

    // ---- normalize + store to multi [B][S][H*64] as half ----
    int b = bh >> 4, h = bh & 15;
#pragma unroll
    for (int mi = 0; mi < 2; mi++) {
        float inv0 = 1.f / l[mi][0], inv1 = 1.f / l[mi][1];
        int srow = qt * 128 + mb[mi] + g;
        uint32_t* op = multi + ((size_t)(b * SEQ) + srow) * 512 + h * 32;
#pragma unroll
        for (int dt = 0; dt < 8; dt++) {
            op[dt * 4 + t]       = fpack(O[mi][dt][0] * inv0, O[mi][dt][1] * inv0);
            op[512 * 8 + dt * 4 + t] = fpack(O[mi][dt][2] * inv1, O[mi][dt][3] * inv1);
        }
    }
}

// ---------------------------------------------------------------------------
// Launch: convert/transpose -> QKV GEMM -> attention -> output GEMM.
// ---------------------------------------------------------------------------
extern "C" void kernel_launch(void* const* d_in, const int* in_sizes, int n_in,
                              void* d_out, int out_size)
{
    const float* x  = (const float*)d_in[0];
    const float* Wq = (const float*)d_in[1];
    const float* bq = (const float*)d_in[2];
    const float* Wk = (const float*)d_in[3];
    const float* bk = (const float*)d_in[4];
    const float* Wv = (const float*)d_in[5];
    const float* bv = (const float*)d_in[6];
    const float* Wo = (const float*)d_in[7];
    const float* bo = (const float*)d_in[8];
    float* out = (float*)d_out;

    uint32_t *qb, *kb, *vb, *mb, *xt, *wqt, *wkt, *wvt, *wot;
    cudaGetSymbolAddress((void**)&qb,  g_q);
    cudaGetSymbolAddress((void**)&kb,  g_k);
    cudaGetSymbolAddress((void**)&vb,  g_v);
    cudaGetSymbolAddress((void**)&mb,  g_multi);
    cudaGetSymbolAddress((void**)&xt,  g_xt);
    cudaGetSymbolAddress((void**)&wqt, g_wqt);
    cudaGetSymbolAddress((void**)&wkt, g_wkt);
    cudaGetSymbolAddress((void**)&wvt, g_wvt);
    cudaGetSymbolAddress((void**)&wot, g_wot);

    cudaFuncSetAttribute(attn_tc,  cudaFuncAttributeMaxDynamicSharedMemorySize, ATT_SMEM_BYTES);
    cudaFuncSetAttribute(gemm_qkv, cudaFuncAttributeMaxDynamicSharedMemorySize, GSMEM_BYTES);
    cudaFuncSetAttribute(gemm_out, cudaFuncAttributeMaxDynamicSharedMemorySize, GSMEM_BYTES);

    conv_x<<<(XW4 + 255) / 256, 256>>>((const float4*)x, (uint2*)xt, XW4);
    dim3 gt(2, 32, 64);
    transw<<<gt, dim3(32, 8)>>>(Wq, Wk, Wv, Wo,
                                (__half*)wqt, (__half*)wkt, (__half*)wvt, (__half*)wot);

    dim3 gq(DM / 128, MROWS / 128, 3);   // (8, 64, 3)
    gemm_qkv<<<gq, 256, GSMEM_BYTES>>>(xt, wqt, wkt, wvt, bq, bk, bv, qb, kb, vb);

    dim3 ga(SEQ / 128, BHN);             // (16, 64)
    attn_tc<<<ga, 128, ATT_SMEM_BYTES>>>(qb, kb, vb, mb);

    dim3 gg(DM / 128, MROWS / 128);      // (8, 64)
    gemm_out<<<gg, 256, GSMEM_BYTES>>>(mb, wot, bo, out);
}